// round 12
// baseline (speedup 1.0000x reference)
#include <cuda_runtime.h>
#include <cuda_fp16.h>
#include <math.h>
#include <stdint.h>

#define B_ROWS 8192
#define MCOLS  8199
#define MPAD   8320
#define H      128
#define EDIM   256
#define NCLS   7
#define NCT    65
#define NBLK   148

// dynamic smem layout (bytes)
#define OFF_A    0          // A tile fp16 (32768)
#define OFF_B0   32768      // B buf0 (32768)
#define OFF_B1   65536      // B buf1 (32768)
#define OFF_LJ   98304
#define OFF_ROWA 98816
#define OFF_ROWM 99840
#define OFF_COLA 100864
#define OFF_COLM 102912
#define SMEM_BYTES 104960

#define C1F ((float)(0.5 / 0.07 * 1.4426950408889634))
#define C0F ((float)((0.5 + 1e-8) / 0.07 * 1.4426950408889634))
#define MAGICF 12582912.0f

__device__ __half g_h[MPAD * H];
__device__ int   g_lab[MPAD];
__device__ int   g_ccount[NCLS];
__device__ float g_allp[NCT * B_ROWS];
__device__ float g_matchp[NCT * B_ROWS];
__device__ float g_acc[2];
__device__ unsigned int g_done;

// deg-4 exp2 poly coefficients (Taylor ln2^k/k!)
#define P4C 0.0096181291f
#define P3C 0.0555041087f
#define P2C 0.2402265069f
#define P1C 0.6931471806f

// scalar version (must match packed path op-for-op for the pad adjustment)
__device__ __forceinline__ float exp2fast(float t) {
    float kf = t + MAGICF;
    int   ki = __float_as_int(kf);
    float n  = kf - MAGICF;
    float r  = t - n;
    float p  = P4C;
    p = fmaf(p, r, P3C);
    p = fmaf(p, r, P2C);
    p = fmaf(p, r, P1C);
    p = fmaf(p, r, 1.0f);
    return p * __int_as_float((ki << 23) + 0x3f800000);
}

__device__ __forceinline__ uint32_t smem_u32(const void* p) {
    uint32_t a;
    asm("{ .reg .u64 t; cvta.to.shared.u64 t, %1; cvt.u32.u64 %0, t; }" : "=r"(a) : "l"(p));
    return a;
}
__device__ __forceinline__ void cpa16(uint32_t dst, const void* src) {
    asm volatile("cp.async.cg.shared.global [%0], [%1], 16;" :: "r"(dst), "l"(src) : "memory");
}
__device__ __forceinline__ void ldsm4(uint32_t* r, uint32_t addr) {
    asm volatile("ldmatrix.sync.aligned.m8n8.x4.shared.b16 {%0,%1,%2,%3}, [%4];"
                 : "=r"(r[0]), "=r"(r[1]), "=r"(r[2]), "=r"(r[3]) : "r"(addr));
}
__device__ __forceinline__ void mma16816(float* d, const uint32_t* a, uint32_t b0, uint32_t b1) {
    asm volatile(
        "mma.sync.aligned.m16n8k16.row.col.f32.f16.f16.f32 "
        "{%0,%1,%2,%3}, {%4,%5,%6,%7}, {%8,%9}, {%0,%1,%2,%3};"
        : "+f"(d[0]), "+f"(d[1]), "+f"(d[2]), "+f"(d[3])
        : "r"(a[0]), "r"(a[1]), "r"(a[2]), "r"(a[3]), "r"(b0), "r"(b1));
}

// packed f32x2 helpers
__device__ __forceinline__ unsigned long long pk2(float lo, float hi) {
    unsigned long long r;
    asm("mov.b64 %0, {%1, %2};" : "=l"(r) : "f"(lo), "f"(hi));
    return r;
}
__device__ __forceinline__ void upk2(unsigned long long v, float& lo, float& hi) {
    asm("mov.b64 {%0, %1}, %2;" : "=f"(lo), "=f"(hi) : "l"(v));
}
__device__ __forceinline__ unsigned long long bcast2(float v) {
    unsigned int b = __float_as_uint(v);
    return ((unsigned long long)b << 32) | b;
}
#define FMA2(d, a, b, c) asm("fma.rn.f32x2 %0, %1, %2, %3;" : "=l"(d) : "l"(a), "l"(b), "l"(c))
#define ADD2(d, a, b)    asm("add.rn.f32x2 %0, %1, %2;"     : "=l"(d) : "l"(a), "l"(b))
#define MUL2(d, a, b)    asm("mul.rn.f32x2 %0, %1, %2;"     : "=l"(d) : "l"(a), "l"(b))

// load one 128x128 fp16 tile (32KB), chunk-XOR swizzled
__device__ __forceinline__ void load_tile(uint32_t dstBase, int r0, int tid) {
    #pragma unroll
    for (int it = 0; it < 8; it++) {
        int idx = tid + it * 256;          // 2048 16B chunks
        int row = idx >> 4;
        int cch = idx & 15;
        const __half* src = g_h + (size_t)(r0 + row) * H + cch * 8;
        uint32_t dst = dstBase + row * 256 + ((cch ^ (row & 7)) << 4);
        cpa16(dst, src);
    }
}

// warp-per-row prep: 1040 blocks x 256 threads = 8320 warrows
__global__ void k_prep(const float* __restrict__ reps, const int* __restrict__ labels,
                       const float* __restrict__ centers, const float* __restrict__ fc_w,
                       const float* __restrict__ fc_b) {
    const int lane = threadIdx.x & 31;
    const int row  = blockIdx.x * 8 + (threadIdx.x >> 5);
    float4 x4 = make_float4(0.f, 0.f, 0.f, 0.f);
    int lab = -1;
    if (row < B_ROWS) {
        x4 = *(const float4*)(reps + (size_t)row * H + lane * 4);
        lab = labels[row];
    } else if (row < MCOLS) {
        int c = row - B_ROWS;
        lab = c;
        const float* cw = centers + c * EDIM;
        float o[4];
        #pragma unroll
        for (int i = 0; i < 4; i++) {
            int t = lane * 4 + i;
            float acc = fc_b[t];
            const float* w = fc_w + (size_t)t * EDIM;
            #pragma unroll 8
            for (int e = 0; e < EDIM; e++) acc = fmaf(cw[e], w[e], acc);
            o[i] = acc;
        }
        x4 = make_float4(o[0], o[1], o[2], o[3]);
    }
    float s = x4.x * x4.x + x4.y * x4.y + x4.z * x4.z + x4.w * x4.w;
    #pragma unroll
    for (int o = 16; o; o >>= 1) s += __shfl_xor_sync(0xffffffffu, s, o);
    float inv = 1.0f / fmaxf(sqrtf(s), 1e-8f);
    __half2 h01 = __floats2half2_rn(x4.x * inv, x4.y * inv);
    __half2 h23 = __floats2half2_rn(x4.z * inv, x4.w * inv);
    uint2 u;
    u.x = *(unsigned int*)&h01;
    u.y = *(unsigned int*)&h23;
    *(uint2*)(g_h + (size_t)row * H + lane * 4) = u;
    if (lane == 0) {
        g_lab[row] = lab;
        if (row < MCOLS) atomicAdd(&g_ccount[lab], 1);
    }
}

__global__ __launch_bounds__(256, 1) void k_main() {
    extern __shared__ char smem[];
    const uint32_t sb = smem_u32(smem);
    const int tid  = threadIdx.x;
    const int wid  = tid >> 5;
    const int lane = tid & 31;
    const int g    = lane >> 2;
    const int tq   = lane & 3;
    const int wr   = wid & 3;      // row-group (32 rows)
    const int wc   = wid >> 2;     // column-group (64 cols)

    const int bid = blockIdx.x;
    const int start = bid * 14 + (bid < 72 ? bid : 72);
    const int cnt = 14 + (bid < 72 ? 1 : 0);

    int t = start, rt = 0;
    while (t >= NCT - rt) { t -= NCT - rt; rt++; }
    int ct = rt + t;

    int* lj = (int*)(smem + OFF_LJ);
    float* rowA = (float*)(smem + OFF_ROWA);
    float* rowM = (float*)(smem + OFF_ROWM);
    float* colA = (float*)(smem + OFF_COLA);
    float* colM = (float*)(smem + OFF_COLM);

    // hoisted packed constants
    const unsigned long long C1_2 = bcast2(C1F);
    const unsigned long long C0_2 = bcast2(C0F);
    const unsigned long long MG2  = bcast2(MAGICF);
    const unsigned long long NMG2 = bcast2(-MAGICF);
    const unsigned long long M1_2 = bcast2(-1.0f);
    const unsigned long long P4_2 = bcast2(P4C);
    const unsigned long long P3_2 = bcast2(P3C);
    const unsigned long long P2_2 = bcast2(P2C);
    const unsigned long long P1_2 = bcast2(P1C);
    const unsigned long long ONE2 = bcast2(1.0f);

    load_tile(sb + OFF_A, rt * 128, tid);
    load_tile(sb + OFF_B0, ct * 128, tid);
    asm volatile("cp.async.commit_group;" ::: "memory");
    int buf = 0;

    for (int k = 0; k < cnt; k++) {
        const int i0 = rt * 128;
        const int j0 = ct * 128;
        const bool isDiag  = (rt == ct);
        const bool needCol = (!isDiag) && (ct < 64);
        int nrt = rt, nct = ct + 1;
        if (nct >= NCT) { nrt = rt + 1; nct = nrt; }

        asm volatile("cp.async.wait_group 0;" ::: "memory");
        __syncthreads();                                   // S0: tiles visible

        if (tid < 128) lj[tid] = g_lab[j0 + tid];
        if (k + 1 < cnt) {
            load_tile(sb + OFF_B0 + (buf ^ 1) * 32768, nct * 128, tid);
            asm volatile("cp.async.commit_group;" ::: "memory");
        }

        // ---- single-pass fp16 MMA ----
        float acc[2][8][4];
        #pragma unroll
        for (int mi = 0; mi < 2; mi++)
            #pragma unroll
            for (int ni = 0; ni < 8; ni++)
                #pragma unroll
                for (int c = 0; c < 4; c++) acc[mi][ni][c] = 0.0f;

        const uint32_t Ab = sb + OFF_A;
        const uint32_t Bb = sb + OFF_B0 + buf * 32768;
        #pragma unroll
        for (int ks = 0; ks < 8; ks++) {
            uint32_t a[2][4];
            #pragma unroll
            for (int mi = 0; mi < 2; mi++) {
                int row = wr * 32 + mi * 16 + (lane & 15);
                int kch = ks * 2 + (lane >> 4);
                ldsm4(a[mi], Ab + row * 256 + ((kch ^ (row & 7)) << 4));
            }
            uint32_t b[4][4];
            #pragma unroll
            for (int nq = 0; nq < 4; nq++) {
                int rowN = wc * 64 + nq * 16 + (lane & 7) + ((lane >> 4) << 3);
                int kch = ks * 2 + ((lane >> 3) & 1);
                ldsm4(b[nq], Bb + rowN * 256 + ((kch ^ (rowN & 7)) << 4));
            }
            #pragma unroll
            for (int mi = 0; mi < 2; mi++)
                #pragma unroll
                for (int ni = 0; ni < 8; ni++)
                    mma16816(acc[mi][ni], a[mi],
                             b[ni >> 1][(ni & 1) * 2], b[ni >> 1][(ni & 1) * 2 + 1]);
        }
        __syncthreads();                                   // S1: MMA done, lj visible

        // ---- packed f32x2 epilogue ----
        int li4[4];
        #pragma unroll
        for (int kk = 0; kk < 4; kk++)
            li4[kk] = g_lab[i0 + wr * 32 + (kk >> 1) * 16 + (kk & 1) * 8 + g];
        int ljr[8][2];
        #pragma unroll
        for (int ni = 0; ni < 8; ni++) {
            ljr[ni][0] = lj[wc * 64 + ni * 8 + tq * 2 + 0];
            ljr[ni][1] = lj[wc * 64 + ni * 8 + tq * 2 + 1];
        }

        unsigned long long rs2[4], rm2[4], cs2[8], cm2[8];
        #pragma unroll
        for (int kk = 0; kk < 4; kk++) { rs2[kk] = 0ull; rm2[kk] = 0ull; }
        #pragma unroll
        for (int ni = 0; ni < 8; ni++) { cs2[ni] = 0ull; cm2[ni] = 0ull; }

        #pragma unroll
        for (int mi = 0; mi < 2; mi++)
            #pragma unroll
            for (int ni = 0; ni < 8; ni++)
                #pragma unroll
                for (int ch = 0; ch < 2; ch++) {
                    const int kk = mi * 2 + ch;
                    unsigned long long a2 = pk2(acc[mi][ni][ch * 2], acc[mi][ni][ch * 2 + 1]);
                    unsigned long long t2, kf2, n2, r2, p2, e2;
                    FMA2(t2, a2, C1_2, C0_2);
                    ADD2(kf2, t2, MG2);
                    ADD2(n2, kf2, NMG2);
                    FMA2(r2, n2, M1_2, t2);        // r = t - n
                    p2 = P4_2;
                    FMA2(p2, p2, r2, P3_2);
                    FMA2(p2, p2, r2, P2_2);
                    FMA2(p2, p2, r2, P1_2);
                    FMA2(p2, p2, r2, ONE2);
                    unsigned int klo = (unsigned int)kf2;
                    unsigned int khi = (unsigned int)(kf2 >> 32);
                    unsigned long long s2 =
                        ((unsigned long long)((khi << 23) + 0x3f800000u) << 32) |
                        (unsigned long long)((klo << 23) + 0x3f800000u);
                    MUL2(e2, p2, s2);
                    if (isDiag) {
                        float elo, ehi;
                        upk2(e2, elo, ehi);
                        int R  = wr * 32 + mi * 16 + ch * 8 + g;
                        int Cb = wc * 64 + ni * 8 + tq * 2;
                        if (R == Cb)     elo = 0.0f;
                        if (R == Cb + 1) ehi = 0.0f;
                        e2 = pk2(elo, ehi);
                    }
                    unsigned long long mask2 =
                        ((li4[kk] == ljr[ni][0]) ? 0x00000000ffffffffull : 0ull) |
                        ((li4[kk] == ljr[ni][1]) ? 0xffffffff00000000ull : 0ull);
                    unsigned long long m2 = e2 & mask2;
                    ADD2(rs2[kk], rs2[kk], e2);
                    ADD2(rm2[kk], rm2[kk], m2);
                    ADD2(cs2[ni], cs2[ni], e2);
                    ADD2(cm2[ni], cm2[ni], m2);
                }

        float rs[4], rm[4];
        #pragma unroll
        for (int kk = 0; kk < 4; kk++) {
            float lo, hi;
            upk2(rs2[kk], lo, hi); rs[kk] = lo + hi;
            upk2(rm2[kk], lo, hi); rm[kk] = lo + hi;
            #pragma unroll
            for (int o = 1; o <= 2; o <<= 1) {
                rs[kk] += __shfl_xor_sync(0xffffffffu, rs[kk], o);
                rm[kk] += __shfl_xor_sync(0xffffffffu, rm[kk], o);
            }
        }
        if (tq == 0) {
            #pragma unroll
            for (int kk = 0; kk < 4; kk++) {
                int R = wr * 32 + (kk >> 1) * 16 + (kk & 1) * 8 + g;
                rowA[wc * 128 + R] = rs[kk];
                rowM[wc * 128 + R] = rm[kk];
            }
        }

        if (needCol) {
            float cs[8][2], cm[8][2];
            #pragma unroll
            for (int ni = 0; ni < 8; ni++) {
                upk2(cs2[ni], cs[ni][0], cs[ni][1]);
                upk2(cm2[ni], cm[ni][0], cm[ni][1]);
            }
            #pragma unroll
            for (int ni = 0; ni < 8; ni++)
                #pragma unroll
                for (int cl = 0; cl < 2; cl++) {
                    #pragma unroll
                    for (int o = 4; o <= 16; o <<= 1) {
                        cs[ni][cl] += __shfl_xor_sync(0xffffffffu, cs[ni][cl], o);
                        cm[ni][cl] += __shfl_xor_sync(0xffffffffu, cm[ni][cl], o);
                    }
                }
            if (g == 0) {
                #pragma unroll
                for (int ni = 0; ni < 8; ni++)
                    #pragma unroll
                    for (int cl = 0; cl < 2; cl++) {
                        int C = wc * 64 + ni * 8 + tq * 2 + cl;
                        colA[wr * 128 + C] = cs[ni][cl];
                        colM[wr * 128 + C] = cm[ni][cl];
                    }
            }
        }
        __syncthreads();                                   // S2

        if (tid < 128) {
            float a = rowA[tid] + rowA[128 + tid];
            float m = rowM[tid] + rowM[128 + tid];
            if (ct == 64) a -= (float)(MPAD - MCOLS) * exp2fast(C0F);
            g_allp[ct * B_ROWS + i0 + tid]   = a;
            g_matchp[ct * B_ROWS + i0 + tid] = m;
            if (needCol) {
                float ca  = colA[tid] + colA[128 + tid] + colA[256 + tid] + colA[384 + tid];
                float cmv = colM[tid] + colM[128 + tid] + colM[256 + tid] + colM[384 + tid];
                g_allp[rt * B_ROWS + j0 + tid]   = ca;
                g_matchp[rt * B_ROWS + j0 + tid] = cmv;
            }
        }

        if (k + 1 < cnt && nrt != rt) {
            load_tile(sb + OFF_A, nrt * 128, tid);
            asm volatile("cp.async.commit_group;" ::: "memory");
        }
        rt = nrt; ct = nct; buf ^= 1;
    }
}

// per-row loss + block reduce + atomic accumulate + merged final (last block)
__global__ void k_rows(float* __restrict__ out) {
    int tid = threadIdx.x;
    int q = tid >> 5, r = tid & 31;
    int i = blockIdx.x * 32 + r;     // 256 blocks
    int c0 = q * 8;
    int cn = (q == 7) ? 9 : 8;
    float all = 0.0f, match = 0.0f;
    #pragma unroll
    for (int k = 0; k < 9; k++) {
        if (k < cn) {
            int ctk = c0 + k;
            all   += g_allp[ctk * B_ROWS + i];
            match += g_matchp[ctk * B_ROWS + i];
        }
    }
    __shared__ float sa[8][32], smm[8][32];
    sa[q][r] = all; smm[q][r] = match;
    __syncthreads();
    if (q == 0) {
        all = 0.0f; match = 0.0f;
        #pragma unroll
        for (int k = 0; k < 8; k++) { all += sa[k][r]; match += smm[k][r]; }
        float pos = match;
        float neg = all - match;
        int lab = g_lab[i];
        float cntv = (float)(g_ccount[lab] - 1);
        float prob = pos / (pos + neg);
        prob = prob / (cntv + 1e-8f);
        float lv = -logf(prob + 1e-8f);
        bool msk = lv > 0.3f;
        float lsum = msk ? lv : 0.0f;
        float lcnt = msk ? 1.0f : 0.0f;
        #pragma unroll
        for (int o = 16; o; o >>= 1) {
            lsum += __shfl_xor_sync(0xffffffffu, lsum, o);
            lcnt += __shfl_xor_sync(0xffffffffu, lcnt, o);
        }
        if (r == 0) {
            atomicAdd(&g_acc[0], lsum);
            atomicAdd(&g_acc[1], lcnt);
            __threadfence();
            unsigned int prev = atomicAdd(&g_done, 1u);
            if (prev == 255u) {
                float s = atomicAdd(&g_acc[0], 0.0f);
                float c = atomicAdd(&g_acc[1], 0.0f);
                out[0] = s / (c + 1e-8f);
                g_acc[0] = 0.0f;
                g_acc[1] = 0.0f;
                g_done = 0u;
                #pragma unroll
                for (int cc = 0; cc < NCLS; cc++) g_ccount[cc] = 0;
            }
        }
    }
}

extern "C" void kernel_launch(void* const* d_in, const int* in_sizes, int n_in,
                              void* d_out, int out_size) {
    const float* reps    = (const float*)d_in[0];
    const int*   labels  = (const int*)d_in[1];
    const float* centers = (const float*)d_in[2];
    const float* fc_w    = (const float*)d_in[3];
    const float* fc_b    = (const float*)d_in[4];
    float* out = (float*)d_out;

    cudaFuncSetAttribute(k_main, cudaFuncAttributeMaxDynamicSharedMemorySize, SMEM_BYTES);

    k_prep<<<1040, 256>>>(reps, labels, centers, fc_w, fc_b);
    k_main<<<NBLK, 256, SMEM_BYTES>>>();
    k_rows<<<256, 256>>>(out);
}

// round 14
// speedup vs baseline: 2.6574x; 2.6574x over previous
#include <cuda_runtime.h>
#include <cuda_fp16.h>
#include <math.h>
#include <stdint.h>

#define B_ROWS 8192
#define MCOLS  8199
#define MPAD   8320
#define H      128
#define EDIM   256
#define NCLS   7
#define NCT    65
#define NBLK   148

// dynamic smem layout (bytes)
#define OFF_A    0          // A tile fp16 (32768)
#define OFF_B0   32768      // B buf0 (32768)
#define OFF_B1   65536      // B buf1 (32768)
#define OFF_LJ   98304
#define OFF_ROWA 98816
#define OFF_ROWM 99840
#define OFF_COLA 100864
#define OFF_COLM 102912
#define SMEM_BYTES 104960

#define C1F ((float)(0.5 / 0.07 * 1.4426950408889634))
#define C0F ((float)((0.5 + 1e-8) / 0.07 * 1.4426950408889634))
#define MAGICF 12582912.0f

__device__ __half g_h[MPAD * H];
__device__ int   g_lab[MPAD];
__device__ int   g_ccount[NCLS];
__device__ float g_allp[NCT * B_ROWS];
__device__ float g_matchp[NCT * B_ROWS];
__device__ float g_acc[2];
__device__ unsigned int g_done;

// deg-4 exp2 poly coefficients
#define P4C 0.0096181291f
#define P3C 0.0555041087f
#define P2C 0.2402265069f
#define P1C 0.6931471806f

// scalar version (must match packed path op-for-op for the pad adjustment)
__device__ __forceinline__ float exp2fast(float t) {
    float kf = t + MAGICF;
    int   ki = __float_as_int(kf);
    float n  = kf - MAGICF;
    float r  = t - n;
    float p  = P4C;
    p = fmaf(p, r, P3C);
    p = fmaf(p, r, P2C);
    p = fmaf(p, r, P1C);
    p = fmaf(p, r, 1.0f);
    return p * __int_as_float((ki << 23) + 0x3f800000);
}

__device__ __forceinline__ uint32_t smem_u32(const void* p) {
    uint32_t a;
    asm("{ .reg .u64 t; cvta.to.shared.u64 t, %1; cvt.u32.u64 %0, t; }" : "=r"(a) : "l"(p));
    return a;
}
__device__ __forceinline__ void cpa16(uint32_t dst, const void* src) {
    asm volatile("cp.async.cg.shared.global [%0], [%1], 16;" :: "r"(dst), "l"(src) : "memory");
}
__device__ __forceinline__ void ldsm4(uint32_t* r, uint32_t addr) {
    asm volatile("ldmatrix.sync.aligned.m8n8.x4.shared.b16 {%0,%1,%2,%3}, [%4];"
                 : "=r"(r[0]), "=r"(r[1]), "=r"(r[2]), "=r"(r[3]) : "r"(addr));
}
__device__ __forceinline__ void mma16816(float* d, const uint32_t* a, uint32_t b0, uint32_t b1) {
    asm volatile(
        "mma.sync.aligned.m16n8k16.row.col.f32.f16.f16.f32 "
        "{%0,%1,%2,%3}, {%4,%5,%6,%7}, {%8,%9}, {%0,%1,%2,%3};"
        : "+f"(d[0]), "+f"(d[1]), "+f"(d[2]), "+f"(d[3])
        : "r"(a[0]), "r"(a[1]), "r"(a[2]), "r"(a[3]), "r"(b0), "r"(b1));
}

// packed f32x2 helpers
__device__ __forceinline__ unsigned long long pk2(float lo, float hi) {
    unsigned long long r;
    asm("mov.b64 %0, {%1, %2};" : "=l"(r) : "f"(lo), "f"(hi));
    return r;
}
__device__ __forceinline__ void upk2(unsigned long long v, float& lo, float& hi) {
    asm("mov.b64 {%0, %1}, %2;" : "=f"(lo), "=f"(hi) : "l"(v));
}
__device__ __forceinline__ unsigned long long bcast2(float v) {
    unsigned int b = __float_as_uint(v);
    return ((unsigned long long)b << 32) | b;
}
#define FMA2(d, a, b, c) asm("fma.rn.f32x2 %0, %1, %2, %3;" : "=l"(d) : "l"(a), "l"(b), "l"(c))
#define ADD2(d, a, b)    asm("add.rn.f32x2 %0, %1, %2;"     : "=l"(d) : "l"(a), "l"(b))
#define MUL2(d, a, b)    asm("mul.rn.f32x2 %0, %1, %2;"     : "=l"(d) : "l"(a), "l"(b))

// load one 128x128 fp16 tile (32KB), chunk-XOR swizzled
__device__ __forceinline__ void load_tile(uint32_t dstBase, int r0, int tid) {
    #pragma unroll
    for (int it = 0; it < 8; it++) {
        int idx = tid + it * 256;          // 2048 16B chunks
        int row = idx >> 4;
        int cch = idx & 15;
        const __half* src = g_h + (size_t)(r0 + row) * H + cch * 8;
        uint32_t dst = dstBase + row * 256 + ((cch ^ (row & 7)) << 4);
        cpa16(dst, src);
    }
}

// k_prep: blocks 0..1023 = warp-per-row over reps (8 rows/block);
//         blocks 1024..1030 = one center each (coalesced warp-cooperative fc) + pad-row zeroing
__global__ void k_prep(const float* __restrict__ reps, const int* __restrict__ labels,
                       const float* __restrict__ centers, const float* __restrict__ fc_w,
                       const float* __restrict__ fc_b) {
    const int tid  = threadIdx.x;
    const int lane = tid & 31;
    const int w    = tid >> 5;

    if (blockIdx.x < 1024) {
        const int row = blockIdx.x * 8 + w;
        float4 x4 = *(const float4*)(reps + (size_t)row * H + lane * 4);
        float s = x4.x * x4.x + x4.y * x4.y + x4.z * x4.z + x4.w * x4.w;
        #pragma unroll
        for (int o = 16; o; o >>= 1) s += __shfl_xor_sync(0xffffffffu, s, o);
        float inv = 1.0f / fmaxf(sqrtf(s), 1e-8f);
        __half2 h01 = __floats2half2_rn(x4.x * inv, x4.y * inv);
        __half2 h23 = __floats2half2_rn(x4.z * inv, x4.w * inv);
        uint2 u;
        u.x = *(unsigned int*)&h01;
        u.y = *(unsigned int*)&h23;
        *(uint2*)(g_h + (size_t)row * H + lane * 4) = u;
        if (lane == 0) {
            int lab = labels[row];
            g_lab[row] = lab;
            atomicAdd(&g_ccount[lab], 1);
        }
        return;
    }

    // center blocks
    const int c = blockIdx.x - 1024;       // 0..6
    __shared__ float scw[EDIM];
    __shared__ float srow[H];
    __shared__ float ws4[4];
    scw[tid] = centers[(size_t)c * EDIM + tid];
    __syncthreads();

    // warp w computes output dims w*16 .. w*16+15, coalesced reads of fc_w rows
    #pragma unroll 4
    for (int d = 0; d < 16; d++) {
        int t = w * 16 + d;
        const float4* wrow = (const float4*)(fc_w + (size_t)t * EDIM);
        float4 a = wrow[lane * 2];
        float4 b = wrow[lane * 2 + 1];
        int e0 = lane * 8;
        float s = a.x * scw[e0] + a.y * scw[e0 + 1] + a.z * scw[e0 + 2] + a.w * scw[e0 + 3]
                + b.x * scw[e0 + 4] + b.y * scw[e0 + 5] + b.z * scw[e0 + 6] + b.w * scw[e0 + 7];
        #pragma unroll
        for (int o = 16; o; o >>= 1) s += __shfl_xor_sync(0xffffffffu, s, o);
        if (lane == 0) srow[t] = s + fc_b[t];
    }
    __syncthreads();

    // normalize (threads 0..127) and emit fp16
    if (tid < 128) {
        float x = srow[tid];
        float s = x * x;
        #pragma unroll
        for (int o = 16; o; o >>= 1) s += __shfl_xor_sync(0xffffffffu, s, o);
        if ((tid & 31) == 0) ws4[tid >> 5] = s;
    }
    __syncthreads();
    if (tid < 128) {
        float tot = ws4[0] + ws4[1] + ws4[2] + ws4[3];
        float inv = 1.0f / fmaxf(sqrtf(tot), 1e-8f);
        int row = B_ROWS + c;
        g_h[(size_t)row * H + tid] = __float2half_rn(srow[tid] * inv);
        if (tid == 0) {
            g_lab[row] = c;
            atomicAdd(&g_ccount[c], 1);
        }
    }

    // zero-fill pad rows 8199..8319 (121 rows, 18 per block) + labels = -1
    #pragma unroll
    for (int rr = 0; rr < 18; rr++) {
        int row = MCOLS + c * 18 + rr;
        if (row < MPAD) {
            if (tid < 64) ((unsigned int*)(g_h + (size_t)row * H))[tid] = 0u;
            if (tid == 0) g_lab[row] = -1;
        }
    }
}

__global__ __launch_bounds__(256, 1) void k_main() {
    extern __shared__ char smem[];
    const uint32_t sb = smem_u32(smem);
    const int tid  = threadIdx.x;
    const int wid  = tid >> 5;
    const int lane = tid & 31;
    const int g    = lane >> 2;
    const int tq   = lane & 3;
    const int wr   = wid & 3;      // row-group (32 rows)
    const int wc   = wid >> 2;     // column-group (64 cols)

    const int bid = blockIdx.x;
    const int start = bid * 14 + (bid < 72 ? bid : 72);
    const int cnt = 14 + (bid < 72 ? 1 : 0);

    int t = start, rt = 0;
    while (t >= NCT - rt) { t -= NCT - rt; rt++; }
    int ct = rt + t;

    int* lj = (int*)(smem + OFF_LJ);
    float* rowA = (float*)(smem + OFF_ROWA);
    float* rowM = (float*)(smem + OFF_ROWM);
    float* colA = (float*)(smem + OFF_COLA);
    float* colM = (float*)(smem + OFF_COLM);

    const unsigned long long C1_2 = bcast2(C1F);
    const unsigned long long C0_2 = bcast2(C0F);
    const unsigned long long MG2  = bcast2(MAGICF);
    const unsigned long long NMG2 = bcast2(-MAGICF);
    const unsigned long long M1_2 = bcast2(-1.0f);
    const unsigned long long P4_2 = bcast2(P4C);
    const unsigned long long P3_2 = bcast2(P3C);
    const unsigned long long P2_2 = bcast2(P2C);
    const unsigned long long P1_2 = bcast2(P1C);
    const unsigned long long ONE2 = bcast2(1.0f);

    load_tile(sb + OFF_A, rt * 128, tid);
    load_tile(sb + OFF_B0, ct * 128, tid);
    asm volatile("cp.async.commit_group;" ::: "memory");
    int buf = 0;

    for (int k = 0; k < cnt; k++) {
        const int i0 = rt * 128;
        const int j0 = ct * 128;
        const bool isDiag  = (rt == ct);
        const bool needCol = (!isDiag) && (ct < 64);
        int nrt = rt, nct = ct + 1;
        if (nct >= NCT) { nrt = rt + 1; nct = nrt; }

        asm volatile("cp.async.wait_group 0;" ::: "memory");
        __syncthreads();                                   // S0: tiles visible

        if (tid < 128) lj[tid] = g_lab[j0 + tid];
        if (k + 1 < cnt) {
            load_tile(sb + OFF_B0 + (buf ^ 1) * 32768, nct * 128, tid);
            asm volatile("cp.async.commit_group;" ::: "memory");
        }

        // ---- single-pass fp16 MMA ----
        float acc[2][8][4];
        #pragma unroll
        for (int mi = 0; mi < 2; mi++)
            #pragma unroll
            for (int ni = 0; ni < 8; ni++)
                #pragma unroll
                for (int c = 0; c < 4; c++) acc[mi][ni][c] = 0.0f;

        const uint32_t Ab = sb + OFF_A;
        const uint32_t Bb = sb + OFF_B0 + buf * 32768;
        #pragma unroll
        for (int ks = 0; ks < 8; ks++) {
            uint32_t a[2][4];
            #pragma unroll
            for (int mi = 0; mi < 2; mi++) {
                int row = wr * 32 + mi * 16 + (lane & 15);
                int kch = ks * 2 + (lane >> 4);
                ldsm4(a[mi], Ab + row * 256 + ((kch ^ (row & 7)) << 4));
            }
            uint32_t b[4][4];
            #pragma unroll
            for (int nq = 0; nq < 4; nq++) {
                int rowN = wc * 64 + nq * 16 + (lane & 7) + ((lane >> 4) << 3);
                int kch = ks * 2 + ((lane >> 3) & 1);
                ldsm4(b[nq], Bb + rowN * 256 + ((kch ^ (rowN & 7)) << 4));
            }
            #pragma unroll
            for (int mi = 0; mi < 2; mi++)
                #pragma unroll
                for (int ni = 0; ni < 8; ni++)
                    mma16816(acc[mi][ni], a[mi],
                             b[ni >> 1][(ni & 1) * 2], b[ni >> 1][(ni & 1) * 2 + 1]);
        }
        __syncthreads();                                   // S1: MMA done, lj visible

        // ---- packed f32x2 epilogue ----
        int li4[4];
        #pragma unroll
        for (int kk = 0; kk < 4; kk++)
            li4[kk] = g_lab[i0 + wr * 32 + (kk >> 1) * 16 + (kk & 1) * 8 + g];
        int ljr[8][2];
        #pragma unroll
        for (int ni = 0; ni < 8; ni++) {
            ljr[ni][0] = lj[wc * 64 + ni * 8 + tq * 2 + 0];
            ljr[ni][1] = lj[wc * 64 + ni * 8 + tq * 2 + 1];
        }

        unsigned long long rs2[4], rm2[4], cs2[8], cm2[8];
        #pragma unroll
        for (int kk = 0; kk < 4; kk++) { rs2[kk] = 0ull; rm2[kk] = 0ull; }
        #pragma unroll
        for (int ni = 0; ni < 8; ni++) { cs2[ni] = 0ull; cm2[ni] = 0ull; }

        #pragma unroll
        for (int mi = 0; mi < 2; mi++)
            #pragma unroll
            for (int ni = 0; ni < 8; ni++)
                #pragma unroll
                for (int ch = 0; ch < 2; ch++) {
                    const int kk = mi * 2 + ch;
                    unsigned long long a2 = pk2(acc[mi][ni][ch * 2], acc[mi][ni][ch * 2 + 1]);
                    unsigned long long t2, kf2, n2, r2, p2, e2;
                    FMA2(t2, a2, C1_2, C0_2);
                    ADD2(kf2, t2, MG2);
                    ADD2(n2, kf2, NMG2);
                    FMA2(r2, n2, M1_2, t2);        // r = t - n
                    p2 = P4_2;
                    FMA2(p2, p2, r2, P3_2);
                    FMA2(p2, p2, r2, P2_2);
                    FMA2(p2, p2, r2, P1_2);
                    FMA2(p2, p2, r2, ONE2);
                    unsigned int klo = (unsigned int)kf2;
                    unsigned int khi = (unsigned int)(kf2 >> 32);
                    unsigned long long s2 =
                        ((unsigned long long)((khi << 23) + 0x3f800000u) << 32) |
                        (unsigned long long)((klo << 23) + 0x3f800000u);
                    MUL2(e2, p2, s2);
                    if (isDiag) {
                        float elo, ehi;
                        upk2(e2, elo, ehi);
                        int R  = wr * 32 + mi * 16 + ch * 8 + g;
                        int Cb = wc * 64 + ni * 8 + tq * 2;
                        if (R == Cb)     elo = 0.0f;
                        if (R == Cb + 1) ehi = 0.0f;
                        e2 = pk2(elo, ehi);
                    }
                    unsigned long long mask2 =
                        ((li4[kk] == ljr[ni][0]) ? 0x00000000ffffffffull : 0ull) |
                        ((li4[kk] == ljr[ni][1]) ? 0xffffffff00000000ull : 0ull);
                    unsigned long long m2 = e2 & mask2;
                    ADD2(rs2[kk], rs2[kk], e2);
                    ADD2(rm2[kk], rm2[kk], m2);
                    ADD2(cs2[ni], cs2[ni], e2);
                    ADD2(cm2[ni], cm2[ni], m2);
                }

        float rs[4], rm[4];
        #pragma unroll
        for (int kk = 0; kk < 4; kk++) {
            float lo, hi;
            upk2(rs2[kk], lo, hi); rs[kk] = lo + hi;
            upk2(rm2[kk], lo, hi); rm[kk] = lo + hi;
            #pragma unroll
            for (int o = 1; o <= 2; o <<= 1) {
                rs[kk] += __shfl_xor_sync(0xffffffffu, rs[kk], o);
                rm[kk] += __shfl_xor_sync(0xffffffffu, rm[kk], o);
            }
        }
        if (tq == 0) {
            #pragma unroll
            for (int kk = 0; kk < 4; kk++) {
                int R = wr * 32 + (kk >> 1) * 16 + (kk & 1) * 8 + g;
                rowA[wc * 128 + R] = rs[kk];
                rowM[wc * 128 + R] = rm[kk];
            }
        }

        if (needCol) {
            float cs[8][2], cm[8][2];
            #pragma unroll
            for (int ni = 0; ni < 8; ni++) {
                upk2(cs2[ni], cs[ni][0], cs[ni][1]);
                upk2(cm2[ni], cm[ni][0], cm[ni][1]);
            }
            #pragma unroll
            for (int ni = 0; ni < 8; ni++)
                #pragma unroll
                for (int cl = 0; cl < 2; cl++) {
                    #pragma unroll
                    for (int o = 4; o <= 16; o <<= 1) {
                        cs[ni][cl] += __shfl_xor_sync(0xffffffffu, cs[ni][cl], o);
                        cm[ni][cl] += __shfl_xor_sync(0xffffffffu, cm[ni][cl], o);
                    }
                }
            if (g == 0) {
                #pragma unroll
                for (int ni = 0; ni < 8; ni++)
                    #pragma unroll
                    for (int cl = 0; cl < 2; cl++) {
                        int C = wc * 64 + ni * 8 + tq * 2 + cl;
                        colA[wr * 128 + C] = cs[ni][cl];
                        colM[wr * 128 + C] = cm[ni][cl];
                    }
            }
        }
        __syncthreads();                                   // S2

        if (tid < 128) {
            float a = rowA[tid] + rowA[128 + tid];
            float m = rowM[tid] + rowM[128 + tid];
            if (ct == 64) a -= (float)(MPAD - MCOLS) * exp2fast(C0F);
            g_allp[ct * B_ROWS + i0 + tid]   = a;
            g_matchp[ct * B_ROWS + i0 + tid] = m;
            if (needCol) {
                float ca  = colA[tid] + colA[128 + tid] + colA[256 + tid] + colA[384 + tid];
                float cmv = colM[tid] + colM[128 + tid] + colM[256 + tid] + colM[384 + tid];
                g_allp[rt * B_ROWS + j0 + tid]   = ca;
                g_matchp[rt * B_ROWS + j0 + tid] = cmv;
            }
        }

        if (k + 1 < cnt && nrt != rt) {
            load_tile(sb + OFF_A, nrt * 128, tid);
            asm volatile("cp.async.commit_group;" ::: "memory");
        }
        rt = nrt; ct = nct; buf ^= 1;
    }
}

// per-row loss + block reduce + atomic accumulate + merged final (last block)
__global__ void k_rows(float* __restrict__ out) {
    int tid = threadIdx.x;
    int q = tid >> 5, r = tid & 31;
    int i = blockIdx.x * 32 + r;     // 256 blocks
    int c0 = q * 8;
    int cn = (q == 7) ? 9 : 8;
    float all = 0.0f, match = 0.0f;
    #pragma unroll
    for (int k = 0; k < 9; k++) {
        if (k < cn) {
            int ctk = c0 + k;
            all   += g_allp[ctk * B_ROWS + i];
            match += g_matchp[ctk * B_ROWS + i];
        }
    }
    __shared__ float sa[8][32], smm[8][32];
    sa[q][r] = all; smm[q][r] = match;
    __syncthreads();
    if (q == 0) {
        all = 0.0f; match = 0.0f;
        #pragma unroll
        for (int k = 0; k < 8; k++) { all += sa[k][r]; match += smm[k][r]; }
        float pos = match;
        float neg = all - match;
        int lab = g_lab[i];
        float cntv = (float)(g_ccount[lab] - 1);
        float prob = pos / (pos + neg);
        prob = prob / (cntv + 1e-8f);
        float lv = -logf(prob + 1e-8f);
        bool msk = lv > 0.3f;
        float lsum = msk ? lv : 0.0f;
        float lcnt = msk ? 1.0f : 0.0f;
        #pragma unroll
        for (int o = 16; o; o >>= 1) {
            lsum += __shfl_xor_sync(0xffffffffu, lsum, o);
            lcnt += __shfl_xor_sync(0xffffffffu, lcnt, o);
        }
        if (r == 0) {
            atomicAdd(&g_acc[0], lsum);
            atomicAdd(&g_acc[1], lcnt);
            __threadfence();
            unsigned int prev = atomicAdd(&g_done, 1u);
            if (prev == 255u) {
                float s = atomicAdd(&g_acc[0], 0.0f);
                float c = atomicAdd(&g_acc[1], 0.0f);
                out[0] = s / (c + 1e-8f);
                g_acc[0] = 0.0f;
                g_acc[1] = 0.0f;
                g_done = 0u;
                #pragma unroll
                for (int cc = 0; cc < NCLS; cc++) g_ccount[cc] = 0;
            }
        }
    }
}

extern "C" void kernel_launch(void* const* d_in, const int* in_sizes, int n_in,
                              void* d_out, int out_size) {
    const float* reps    = (const float*)d_in[0];
    const int*   labels  = (const int*)d_in[1];
    const float* centers = (const float*)d_in[2];
    const float* fc_w    = (const float*)d_in[3];
    const float* fc_b    = (const float*)d_in[4];
    float* out = (float*)d_out;

    cudaFuncSetAttribute(k_main, cudaFuncAttributeMaxDynamicSharedMemorySize, SMEM_BYTES);

    k_prep<<<1031, 256>>>(reps, labels, centers, fc_w, fc_b);
    k_main<<<NBLK, 256, SMEM_BYTES>>>();
    k_rows<<<256, 256>>>(out);
}

// round 17
// speedup vs baseline: 3.1001x; 1.1666x over previous
#include <cuda_runtime.h>
#include <cuda_fp16.h>
#include <math.h>
#include <stdint.h>

#define B_ROWS 8192
#define MCOLS  8199
#define MPAD   8320
#define H      128
#define EDIM   256
#define NCLS   7
#define NCT    65
#define NBLK   296

// dynamic smem layout (bytes)
#define OFF_A    0          // A tile fp16 (32768)
#define OFF_B0   32768      // B buf0 (32768)
#define OFF_B1   65536      // B buf1 (32768)
#define OFF_LJ   98304
#define OFF_ROWA 98816
#define OFF_ROWM 99840
#define OFF_COLA 100864
#define OFF_COLM 102912
#define SMEM_BYTES 104960

#define C1F ((float)(0.5 / 0.07 * 1.4426950408889634))
#define C0F ((float)((0.5 + 1e-8) / 0.07 * 1.4426950408889634))
#define MAGICF 12582912.0f

__device__ __half g_h[MPAD * H];
__device__ int   g_lab[MPAD];
__device__ int   g_ccount[NCLS];
__device__ float g_allp[NCT * B_ROWS];
__device__ float g_matchp[NCT * B_ROWS];
__device__ float g_acc[2];
__device__ unsigned int g_done;

// deg-4 exp2 poly coefficients
#define P4C 0.0096181291f
#define P3C 0.0555041087f
#define P2C 0.2402265069f
#define P1C 0.6931471806f

// scalar version (must match packed path op-for-op for the pad adjustment)
__device__ __forceinline__ float exp2fast(float t) {
    float kf = t + MAGICF;
    int   ki = __float_as_int(kf);
    float n  = kf - MAGICF;
    float r  = t - n;
    float p  = P4C;
    p = fmaf(p, r, P3C);
    p = fmaf(p, r, P2C);
    p = fmaf(p, r, P1C);
    p = fmaf(p, r, 1.0f);
    return p * __int_as_float((ki << 23) + 0x3f800000);
}

__device__ __forceinline__ uint32_t smem_u32(const void* p) {
    uint32_t a;
    asm("{ .reg .u64 t; cvta.to.shared.u64 t, %1; cvt.u32.u64 %0, t; }" : "=r"(a) : "l"(p));
    return a;
}
__device__ __forceinline__ void cpa16(uint32_t dst, const void* src) {
    asm volatile("cp.async.cg.shared.global [%0], [%1], 16;" :: "r"(dst), "l"(src) : "memory");
}
__device__ __forceinline__ void ldsm4(uint32_t* r, uint32_t addr) {
    asm volatile("ldmatrix.sync.aligned.m8n8.x4.shared.b16 {%0,%1,%2,%3}, [%4];"
                 : "=r"(r[0]), "=r"(r[1]), "=r"(r[2]), "=r"(r[3]) : "r"(addr));
}
__device__ __forceinline__ void mma16816(float* d, const uint32_t* a, uint32_t b0, uint32_t b1) {
    asm volatile(
        "mma.sync.aligned.m16n8k16.row.col.f32.f16.f16.f32 "
        "{%0,%1,%2,%3}, {%4,%5,%6,%7}, {%8,%9}, {%0,%1,%2,%3};"
        : "+f"(d[0]), "+f"(d[1]), "+f"(d[2]), "+f"(d[3])
        : "r"(a[0]), "r"(a[1]), "r"(a[2]), "r"(a[3]), "r"(b0), "r"(b1));
}

// packed f32x2 helpers
__device__ __forceinline__ unsigned long long pk2(float lo, float hi) {
    unsigned long long r;
    asm("mov.b64 %0, {%1, %2};" : "=l"(r) : "f"(lo), "f"(hi));
    return r;
}
__device__ __forceinline__ void upk2(unsigned long long v, float& lo, float& hi) {
    asm("mov.b64 {%0, %1}, %2;" : "=f"(lo), "=f"(hi) : "l"(v));
}
__device__ __forceinline__ unsigned long long bcast2(float v) {
    unsigned int b = __float_as_uint(v);
    return ((unsigned long long)b << 32) | b;
}
#define FMA2(d, a, b, c) asm("fma.rn.f32x2 %0, %1, %2, %3;" : "=l"(d) : "l"(a), "l"(b), "l"(c))
#define ADD2(d, a, b)    asm("add.rn.f32x2 %0, %1, %2;"     : "=l"(d) : "l"(a), "l"(b))
#define MUL2(d, a, b)    asm("mul.rn.f32x2 %0, %1, %2;"     : "=l"(d) : "l"(a), "l"(b))

// load one 128x128 fp16 tile (32KB), chunk-XOR swizzled
__device__ __forceinline__ void load_tile(uint32_t dstBase, int r0, int tid) {
    #pragma unroll
    for (int it = 0; it < 8; it++) {
        int idx = tid + it * 256;          // 2048 16B chunks
        int row = idx >> 4;
        int cch = idx & 15;
        const __half* src = g_h + (size_t)(r0 + row) * H + cch * 8;
        uint32_t dst = dstBase + row * 256 + ((cch ^ (row & 7)) << 4);
        cpa16(dst, src);
    }
}

// k_prep: blocks 0..255 = 4 rows/warp over reps (32 rows/block, MLP=4);
//         blocks 256..262 = one center each + pad-row zeroing
__global__ void k_prep(const float* __restrict__ reps, const int* __restrict__ labels,
                       const float* __restrict__ centers, const float* __restrict__ fc_w,
                       const float* __restrict__ fc_b) {
    const int tid  = threadIdx.x;
    const int lane = tid & 31;
    const int w    = tid >> 5;

    if (blockIdx.x < 256) {
        const int r0 = blockIdx.x * 32 + w * 4;
        float4 x[4];
        #pragma unroll
        for (int i = 0; i < 4; i++)
            x[i] = *(const float4*)(reps + (size_t)(r0 + i) * H + lane * 4);
        float s[4];
        #pragma unroll
        for (int i = 0; i < 4; i++)
            s[i] = x[i].x * x[i].x + x[i].y * x[i].y + x[i].z * x[i].z + x[i].w * x[i].w;
        #pragma unroll
        for (int o = 16; o; o >>= 1)
            #pragma unroll
            for (int i = 0; i < 4; i++)
                s[i] += __shfl_xor_sync(0xffffffffu, s[i], o);
        #pragma unroll
        for (int i = 0; i < 4; i++) {
            float inv = 1.0f / fmaxf(sqrtf(s[i]), 1e-8f);
            __half2 h01 = __floats2half2_rn(x[i].x * inv, x[i].y * inv);
            __half2 h23 = __floats2half2_rn(x[i].z * inv, x[i].w * inv);
            uint2 u;
            u.x = *(unsigned int*)&h01;
            u.y = *(unsigned int*)&h23;
            *(uint2*)(g_h + (size_t)(r0 + i) * H + lane * 4) = u;
        }
        if (lane < 4) {
            int lab = labels[r0 + lane];
            g_lab[r0 + lane] = lab;
            atomicAdd(&g_ccount[lab], 1);
        }
        return;
    }

    // center blocks
    const int c = blockIdx.x - 256;        // 0..6
    __shared__ float scw[EDIM];
    __shared__ float srow[H];
    __shared__ float ws4[4];
    scw[tid] = centers[(size_t)c * EDIM + tid];
    __syncthreads();

    #pragma unroll 4
    for (int d = 0; d < 16; d++) {
        int t = w * 16 + d;
        const float4* wrow = (const float4*)(fc_w + (size_t)t * EDIM);
        float4 a = wrow[lane * 2];
        float4 b = wrow[lane * 2 + 1];
        int e0 = lane * 8;
        float s = a.x * scw[e0] + a.y * scw[e0 + 1] + a.z * scw[e0 + 2] + a.w * scw[e0 + 3]
                + b.x * scw[e0 + 4] + b.y * scw[e0 + 5] + b.z * scw[e0 + 6] + b.w * scw[e0 + 7];
        #pragma unroll
        for (int o = 16; o; o >>= 1) s += __shfl_xor_sync(0xffffffffu, s, o);
        if (lane == 0) srow[t] = s + fc_b[t];
    }
    __syncthreads();

    if (tid < 128) {
        float x = srow[tid];
        float s = x * x;
        #pragma unroll
        for (int o = 16; o; o >>= 1) s += __shfl_xor_sync(0xffffffffu, s, o);
        if ((tid & 31) == 0) ws4[tid >> 5] = s;
    }
    __syncthreads();
    if (tid < 128) {
        float tot = ws4[0] + ws4[1] + ws4[2] + ws4[3];
        float inv = 1.0f / fmaxf(sqrtf(tot), 1e-8f);
        int row = B_ROWS + c;
        g_h[(size_t)row * H + tid] = __float2half_rn(srow[tid] * inv);
        if (tid == 0) {
            g_lab[row] = c;
            atomicAdd(&g_ccount[c], 1);
        }
    }

    // zero-fill pad rows 8199..8319 + labels = -1
    #pragma unroll
    for (int rr = 0; rr < 18; rr++) {
        int row = MCOLS + c * 18 + rr;
        if (row < MPAD) {
            if (tid < 64) ((unsigned int*)(g_h + (size_t)row * H))[tid] = 0u;
            if (tid == 0) g_lab[row] = -1;
        }
    }
}

__global__ __launch_bounds__(256, 2) void k_main() {
    extern __shared__ char smem[];
    const uint32_t sb = smem_u32(smem);
    const int tid  = threadIdx.x;
    const int wid  = tid >> 5;
    const int lane = tid & 31;
    const int g    = lane >> 2;
    const int tq   = lane & 3;
    const int wr   = wid & 3;      // row-group (32 rows)
    const int wc   = wid >> 2;     // column-group (64 cols)

    const int bid = blockIdx.x;
    const int start = bid * 7 + (bid < 72 ? bid : 72);
    const int cnt = 7 + (bid < 72 ? 1 : 0);

    int t = start, rt = 0;
    while (t >= NCT - rt) { t -= NCT - rt; rt++; }
    int ct = rt + t;

    int* lj = (int*)(smem + OFF_LJ);
    float* rowA = (float*)(smem + OFF_ROWA);
    float* rowM = (float*)(smem + OFF_ROWM);
    float* colA = (float*)(smem + OFF_COLA);
    float* colM = (float*)(smem + OFF_COLM);

    const unsigned long long C1_2 = bcast2(C1F);
    const unsigned long long C0_2 = bcast2(C0F);
    const unsigned long long MG2  = bcast2(MAGICF);
    const unsigned long long NMG2 = bcast2(-MAGICF);
    const unsigned long long M1_2 = bcast2(-1.0f);
    const unsigned long long P4_2 = bcast2(P4C);
    const unsigned long long P3_2 = bcast2(P3C);
    const unsigned long long P2_2 = bcast2(P2C);
    const unsigned long long P1_2 = bcast2(P1C);
    const unsigned long long ONE2 = bcast2(1.0f);

    load_tile(sb + OFF_A, rt * 128, tid);
    load_tile(sb + OFF_B0, ct * 128, tid);
    asm volatile("cp.async.commit_group;" ::: "memory");
    int buf = 0;

    for (int k = 0; k < cnt; k++) {
        const int i0 = rt * 128;
        const int j0 = ct * 128;
        const bool isDiag  = (rt == ct);
        const bool needCol = (!isDiag) && (ct < 64);
        int nrt = rt, nct = ct + 1;
        if (nct >= NCT) { nrt = rt + 1; nct = nrt; }

        asm volatile("cp.async.wait_group 0;" ::: "memory");
        __syncthreads();                                   // S0: tiles visible

        if (tid < 128) lj[tid] = g_lab[j0 + tid];
        if (k + 1 < cnt) {
            load_tile(sb + OFF_B0 + (buf ^ 1) * 32768, nct * 128, tid);
            asm volatile("cp.async.commit_group;" ::: "memory");
        }

        // ---- single-pass fp16 MMA ----
        float acc[2][8][4];
        #pragma unroll
        for (int mi = 0; mi < 2; mi++)
            #pragma unroll
            for (int ni = 0; ni < 8; ni++)
                #pragma unroll
                for (int c = 0; c < 4; c++) acc[mi][ni][c] = 0.0f;

        const uint32_t Ab = sb + OFF_A;
        const uint32_t Bb = sb + OFF_B0 + buf * 32768;
        #pragma unroll
        for (int ks = 0; ks < 8; ks++) {
            uint32_t a[2][4];
            #pragma unroll
            for (int mi = 0; mi < 2; mi++) {
                int row = wr * 32 + mi * 16 + (lane & 15);
                int kch = ks * 2 + (lane >> 4);
                ldsm4(a[mi], Ab + row * 256 + ((kch ^ (row & 7)) << 4));
            }
            uint32_t b[4][4];
            #pragma unroll
            for (int nq = 0; nq < 4; nq++) {
                int rowN = wc * 64 + nq * 16 + (lane & 7) + ((lane >> 4) << 3);
                int kch = ks * 2 + ((lane >> 3) & 1);
                ldsm4(b[nq], Bb + rowN * 256 + ((kch ^ (rowN & 7)) << 4));
            }
            #pragma unroll
            for (int mi = 0; mi < 2; mi++)
                #pragma unroll
                for (int ni = 0; ni < 8; ni++)
                    mma16816(acc[mi][ni], a[mi],
                             b[ni >> 1][(ni & 1) * 2], b[ni >> 1][(ni & 1) * 2 + 1]);
        }
        __syncthreads();                                   // S1: MMA done, lj visible

        // ---- packed f32x2 epilogue, ni-outer to cap live registers ----
        int li4[4];
        #pragma unroll
        for (int kk = 0; kk < 4; kk++)
            li4[kk] = g_lab[i0 + wr * 32 + (kk >> 1) * 16 + (kk & 1) * 8 + g];

        unsigned long long rs2[4], rm2[4];
        #pragma unroll
        for (int kk = 0; kk < 4; kk++) { rs2[kk] = 0ull; rm2[kk] = 0ull; }

        #pragma unroll
        for (int ni = 0; ni < 8; ni++) {
            int lj0 = lj[wc * 64 + ni * 8 + tq * 2 + 0];
            int lj1 = lj[wc * 64 + ni * 8 + tq * 2 + 1];
            unsigned long long cs2 = 0ull, cm2 = 0ull;
            #pragma unroll
            for (int mi = 0; mi < 2; mi++)
                #pragma unroll
                for (int ch = 0; ch < 2; ch++) {
                    const int kk = mi * 2 + ch;
                    unsigned long long a2 = pk2(acc[mi][ni][ch * 2], acc[mi][ni][ch * 2 + 1]);
                    unsigned long long t2, kf2, n2, r2, p2, e2;
                    FMA2(t2, a2, C1_2, C0_2);
                    ADD2(kf2, t2, MG2);
                    ADD2(n2, kf2, NMG2);
                    FMA2(r2, n2, M1_2, t2);        // r = t - n
                    p2 = P4_2;
                    FMA2(p2, p2, r2, P3_2);
                    FMA2(p2, p2, r2, P2_2);
                    FMA2(p2, p2, r2, P1_2);
                    FMA2(p2, p2, r2, ONE2);
                    unsigned int klo = (unsigned int)kf2;
                    unsigned int khi = (unsigned int)(kf2 >> 32);
                    unsigned long long s2 =
                        ((unsigned long long)((khi << 23) + 0x3f800000u) << 32) |
                        (unsigned long long)((klo << 23) + 0x3f800000u);
                    MUL2(e2, p2, s2);
                    if (isDiag) {
                        float elo, ehi;
                        upk2(e2, elo, ehi);
                        int R  = wr * 32 + mi * 16 + ch * 8 + g;
                        int Cb = wc * 64 + ni * 8 + tq * 2;
                        if (R == Cb)     elo = 0.0f;
                        if (R == Cb + 1) ehi = 0.0f;
                        e2 = pk2(elo, ehi);
                    }
                    unsigned long long mask2 =
                        ((li4[kk] == lj0) ? 0x00000000ffffffffull : 0ull) |
                        ((li4[kk] == lj1) ? 0xffffffff00000000ull : 0ull);
                    unsigned long long m2 = e2 & mask2;
                    ADD2(rs2[kk], rs2[kk], e2);
                    ADD2(rm2[kk], rm2[kk], m2);
                    ADD2(cs2, cs2, e2);
                    ADD2(cm2, cm2, m2);
                }
            if (needCol) {
                float csl, csh, cml, cmh;
                upk2(cs2, csl, csh);
                upk2(cm2, cml, cmh);
                #pragma unroll
                for (int o = 4; o <= 16; o <<= 1) {
                    csl += __shfl_xor_sync(0xffffffffu, csl, o);
                    csh += __shfl_xor_sync(0xffffffffu, csh, o);
                    cml += __shfl_xor_sync(0xffffffffu, cml, o);
                    cmh += __shfl_xor_sync(0xffffffffu, cmh, o);
                }
                if (g == 0) {
                    int C = wc * 64 + ni * 8 + tq * 2;
                    colA[wr * 128 + C]     = csl;
                    colA[wr * 128 + C + 1] = csh;
                    colM[wr * 128 + C]     = cml;
                    colM[wr * 128 + C + 1] = cmh;
                }
            }
        }

        float rs[4], rm[4];
        #pragma unroll
        for (int kk = 0; kk < 4; kk++) {
            float lo, hi;
            upk2(rs2[kk], lo, hi); rs[kk] = lo + hi;
            upk2(rm2[kk], lo, hi); rm[kk] = lo + hi;
            #pragma unroll
            for (int o = 1; o <= 2; o <<= 1) {
                rs[kk] += __shfl_xor_sync(0xffffffffu, rs[kk], o);
                rm[kk] += __shfl_xor_sync(0xffffffffu, rm[kk], o);
            }
        }
        if (tq == 0) {
            #pragma unroll
            for (int kk = 0; kk < 4; kk++) {
                int R = wr * 32 + (kk >> 1) * 16 + (kk & 1) * 8 + g;
                rowA[wc * 128 + R] = rs[kk];
                rowM[wc * 128 + R] = rm[kk];
            }
        }
        __syncthreads();                                   // S2

        if (tid < 128) {
            float a = rowA[tid] + rowA[128 + tid];
            float m = rowM[tid] + rowM[128 + tid];
            if (ct == 64) a -= (float)(MPAD - MCOLS) * exp2fast(C0F);
            g_allp[ct * B_ROWS + i0 + tid]   = a;
            g_matchp[ct * B_ROWS + i0 + tid] = m;
            if (needCol) {
                float ca  = colA[tid] + colA[128 + tid] + colA[256 + tid] + colA[384 + tid];
                float cmv = colM[tid] + colM[128 + tid] + colM[256 + tid] + colM[384 + tid];
                g_allp[rt * B_ROWS + j0 + tid]   = ca;
                g_matchp[rt * B_ROWS + j0 + tid] = cmv;
            }
        }

        if (k + 1 < cnt && nrt != rt) {
            load_tile(sb + OFF_A, nrt * 128, tid);
            asm volatile("cp.async.commit_group;" ::: "memory");
        }
        rt = nrt; ct = nct; buf ^= 1;
    }
}

// per-row loss + block reduce + atomic accumulate + merged final (last block)
__global__ void k_rows(float* __restrict__ out) {
    int tid = threadIdx.x;
    int q = tid >> 5, r = tid & 31;
    int i = blockIdx.x * 32 + r;     // 256 blocks
    int c0 = q * 8;
    int cn = (q == 7) ? 9 : 8;
    float all = 0.0f, match = 0.0f;
    #pragma unroll
    for (int k = 0; k < 9; k++) {
        if (k < cn) {
            int ctk = c0 + k;
            all   += g_allp[ctk * B_ROWS + i];
            match += g_matchp[ctk * B_ROWS + i];
        }
    }
    __shared__ float sa[8][32], smm[8][32];
    sa[q][r] = all; smm[q][r] = match;
    __syncthreads();
    if (q == 0) {
        all = 0.0f; match = 0.0f;
        #pragma unroll
        for (int k = 0; k < 8; k++) { all += sa[k][r]; match += smm[k][r]; }
        float pos = match;
        float neg = all - match;
        int lab = g_lab[i];
        float cntv = (float)(g_ccount[lab] - 1);
        float prob = pos / (pos + neg);
        prob = prob / (cntv + 1e-8f);
        float lv = -logf(prob + 1e-8f);
        bool msk = lv > 0.3f;
        float lsum = msk ? lv : 0.0f;
        float lcnt = msk ? 1.0f : 0.0f;
        #pragma unroll
        for (int o = 16; o; o >>= 1) {
            lsum += __shfl_xor_sync(0xffffffffu, lsum, o);
            lcnt += __shfl_xor_sync(0xffffffffu, lcnt, o);
        }
        if (r == 0) {
            atomicAdd(&g_acc[0], lsum);
            atomicAdd(&g_acc[1], lcnt);
            __threadfence();
            unsigned int prev = atomicAdd(&g_done, 1u);
            if (prev == 255u) {
                float s = atomicAdd(&g_acc[0], 0.0f);
                float c = atomicAdd(&g_acc[1], 0.0f);
                out[0] = s / (c + 1e-8f);
                g_acc[0] = 0.0f;
                g_acc[1] = 0.0f;
                g_done = 0u;
                #pragma unroll
                for (int cc = 0; cc < NCLS; cc++) g_ccount[cc] = 0;
            }
        }
    }
}

extern "C" void kernel_launch(void* const* d_in, const int* in_sizes, int n_in,
                              void* d_out, int out_size) {
    const float* reps    = (const float*)d_in[0];
    const int*   labels  = (const int*)d_in[1];
    const float* centers = (const float*)d_in[2];
    const float* fc_w    = (const float*)d_in[3];
    const float* fc_b    = (const float*)d_in[4];
    float* out = (float*)d_out;

    cudaFuncSetAttribute(k_main, cudaFuncAttributeMaxDynamicSharedMemorySize, SMEM_BYTES);

    k_prep<<<263, 256>>>(reps, labels, centers, fc_w, fc_b);
    k_main<<<NBLK, 256, SMEM_BYTES>>>();
    k_rows<<<256, 256>>>(out);
}